// round 12
// baseline (speedup 1.0000x reference)
#include <cuda_runtime.h>
#include <cstdint>

#define NN   512
#define JJ   48
#define EE   (NN*JJ)
#define MIDC 128
#define EPSL 1e-5f

// ---------------- device scratch ----------------
__device__ int g_mask_mode;                         // 0 = 1-byte bool, 1 = float32, 2 = int32
__device__ __align__(16) float g_h2[(size_t)4 * EE * MIDC];   // ~50 MB
__device__ __align__(16) float g_P[(size_t)NN * MIDC * 224];  // ~59 MB
__device__ __align__(16) float g_S[NN * 224];
__device__ float g_den[NN];
__device__ __align__(16) float g_part[32 * NN * 64];          // per-mid-chunk partials (4 MB)

// ---------------- K1: per-edge radial MLP (+ mask dtype detect in block 0) ----------------
__global__ __launch_bounds__(256) void k1_mlp(
    const float* __restrict__ rel, const unsigned char* __restrict__ mb,
    const float* __restrict__ w1, const float* __restrict__ b1,
    const float* __restrict__ g1, const float* __restrict__ be1,
    const float* __restrict__ w2, const float* __restrict__ b2,
    const float* __restrict__ g2, const float* __restrict__ be2)
{
    __shared__ float h1s[32][MIDC];
    const int t = threadIdx.x, lane = t & 31, wp = t >> 5;
    const int e0 = blockIdx.x * 32;
    const int cg = t & 31, rg = t >> 5;

    // mask dtype detection (block 0, warp 0): sample 2048 elements' byte patterns
    if (blockIdx.x == 0 && wp == 0) {
        int l1 = 0, l3 = 0;
        for (int i = lane * 4; i < 8192; i += 128) {
            if (mb[i + 1]) l1++;              // nonzero -> 1-byte bool data
            if (mb[i + 3] == 0x3Fu) l3++;     // top byte of float 1.0f
        }
        const unsigned u1 = __ballot_sync(0xffffffffu, l1 > 0);
        const unsigned u3 = __ballot_sync(0xffffffffu, l3 > 0);
        if (lane == 0) g_mask_mode = u1 ? 0 : (u3 ? 1 : 2);
    }

    for (int p = 0; p < 4; ++p) {
        const float* w1p = w1 + p * MIDC;  const float* b1p = b1 + p * MIDC;
        const float* g1p = g1 + p * MIDC;  const float* be1p = be1 + p * MIDC;

        #pragma unroll
        for (int q = 0; q < 4; ++q) {
            const int le = wp * 4 + q;
            const float d = rel[e0 + le];
            float a[4];
            #pragma unroll
            for (int s_ = 0; s_ < 4; ++s_) {
                int c = lane + 32 * s_;
                a[s_] = fmaf(d, w1p[c], b1p[c]);
            }
            float s = a[0] + a[1] + a[2] + a[3];
            float s2 = a[0]*a[0] + a[1]*a[1] + a[2]*a[2] + a[3]*a[3];
            #pragma unroll
            for (int off = 16; off; off >>= 1) {
                s  += __shfl_xor_sync(0xffffffffu, s,  off);
                s2 += __shfl_xor_sync(0xffffffffu, s2, off);
            }
            const float mu  = s * 0.0078125f;
            const float inv = rsqrtf(fmaf(-mu, mu, s2 * 0.0078125f) + EPSL);
            #pragma unroll
            for (int s_ = 0; s_ < 4; ++s_) {
                int c = lane + 32 * s_;
                h1s[le][c] = fmaxf(fmaf((a[s_] - mu) * inv, g1p[c], be1p[c]), 0.f);
            }
        }
        __syncwarp();

        float acc[4][4];
        #pragma unroll
        for (int q = 0; q < 4; ++q)
            acc[q][0] = acc[q][1] = acc[q][2] = acc[q][3] = 0.f;
        const float4* w2p = (const float4*)(w2 + p * MIDC * MIDC);
        #pragma unroll 4
        for (int k = 0; k < MIDC; ++k) {
            float4 wv = w2p[k * 32 + cg];
            #pragma unroll
            for (int q = 0; q < 4; ++q) {
                float av = h1s[rg * 4 + q][k];
                acc[q][0] = fmaf(av, wv.x, acc[q][0]);
                acc[q][1] = fmaf(av, wv.y, acc[q][1]);
                acc[q][2] = fmaf(av, wv.z, acc[q][2]);
                acc[q][3] = fmaf(av, wv.w, acc[q][3]);
            }
        }
        const float4 b2v  = ((const float4*)(b2  + p * MIDC))[cg];
        const float4 g2v  = ((const float4*)(g2  + p * MIDC))[cg];
        const float4 be2v = ((const float4*)(be2 + p * MIDC))[cg];
        #pragma unroll
        for (int q = 0; q < 4; ++q) {
            float v0 = acc[q][0] + b2v.x, v1 = acc[q][1] + b2v.y;
            float v2 = acc[q][2] + b2v.z, v3 = acc[q][3] + b2v.w;
            float s  = v0 + v1 + v2 + v3;
            float s2 = v0*v0 + v1*v1 + v2*v2 + v3*v3;
            #pragma unroll
            for (int off = 16; off; off >>= 1) {
                s  += __shfl_xor_sync(0xffffffffu, s,  off);
                s2 += __shfl_xor_sync(0xffffffffu, s2, off);
            }
            const float mu  = s * 0.0078125f;
            const float inv = rsqrtf(fmaf(-mu, mu, s2 * 0.0078125f) + EPSL);
            float4 o;
            o.x = fmaxf(fmaf((v0 - mu) * inv, g2v.x, be2v.x), 0.f);
            o.y = fmaxf(fmaf((v1 - mu) * inv, g2v.y, be2v.y), 0.f);
            o.z = fmaxf(fmaf((v2 - mu) * inv, g2v.z, be2v.z), 0.f);
            o.w = fmaxf(fmaf((v3 - mu) * inv, g2v.w, be2v.w), 0.f);
            ((float4*)(g_h2 + ((size_t)p * EE + e0 + rg * 4 + q) * MIDC))[cg] = o;
        }
        __syncwarp();
    }
}

// ---------------- kP: per-(node,pair) P = h2^T @ s, plus S sums + denom ----------------
template<int D>
__device__ __forceinline__ void pgemm(const float* __restrict__ h2s,
                                      const float* __restrict__ sArr,
                                      float* __restrict__ Pout, int t)
{
    constexpr int DPT = D / 8;
    const int mid0 = (t & 31) * 4, d0 = (t >> 5) * DPT;
    float acc[4][DPT];
    #pragma unroll
    for (int m = 0; m < 4; ++m)
        #pragma unroll
        for (int d = 0; d < DPT; ++d) acc[m][d] = 0.f;

    #pragma unroll 2
    for (int j = 0; j < JJ; ++j) {
        const float4 hv = *(const float4*)(h2s + j * MIDC + mid0);
        float sv[DPT];
        #pragma unroll
        for (int d = 0; d < DPT; ++d) sv[d] = sArr[j * D + d0 + d];
        #pragma unroll
        for (int d = 0; d < DPT; ++d) {
            acc[0][d] = fmaf(hv.x, sv[d], acc[0][d]);
            acc[1][d] = fmaf(hv.y, sv[d], acc[1][d]);
            acc[2][d] = fmaf(hv.z, sv[d], acc[2][d]);
            acc[3][d] = fmaf(hv.w, sv[d], acc[3][d]);
        }
    }
    #pragma unroll
    for (int m = 0; m < 4; ++m)
        #pragma unroll
        for (int d = 0; d < DPT; ++d)
            Pout[(size_t)(mid0 + m) * 224 + d0 + d] = acc[m][d];
}

#define KP_SMEM_FLOATS 15424

__global__ __launch_bounds__(256) void k_P(
    const float* __restrict__ x0, const float* __restrict__ x1,
    const int* __restrict__ nidx, const void* __restrict__ maskp,
    const float* __restrict__ b00, const float* __restrict__ b01,
    const float* __restrict__ b10, const float* __restrict__ b11)
{
    extern __shared__ float sm[];
    float* h2s  = sm;
    float* sArr = sm + 6144;
    float* xg   = sm + 13056;
    float* mskf = sm + 15360;

    const int n = blockIdx.x, p = blockIdx.y, t = threadIdx.x;
    const int base = n * JJ;

    {
        const float4* src = (const float4*)(g_h2 + ((size_t)p * EE + base) * MIDC);
        float4* dst = (float4*)h2s;
        #pragma unroll
        for (int i = t; i < 1536; i += 256) dst[i] = src[i];
    }
    if (t < 48) {
        const int j = t;
        const int mode = g_mask_mode;
        float mf;
        if (mode == 0)      mf = ((const unsigned char*)maskp)[base + j] ? 1.f : 0.f;
        else if (mode == 1) mf = (((const float*)maskp)[base + j] != 0.f) ? 1.f : 0.f;
        else                mf = ((const int*)maskp)[base + j] ? 1.f : 0.f;
        mskf[j] = mf;
        const int nb = nidx[base + j];
        if (p < 2) {
            #pragma unroll
            for (int i = 0; i < 16; ++i) xg[j * 16 + i] = mf * x0[nb * 16 + i];
        } else {
            #pragma unroll
            for (int i = 0; i < 48; ++i) xg[j * 48 + i] = x1[nb * 48 + i];
        }
    }
    __syncthreads();

    if (p == 0) {
        for (int idx = t; idx < 48 * 16; idx += 256) {
            const int j = idx >> 4, i = idx & 15;
            sArr[idx] = b00[base + j] * xg[j * 16 + i];
        }
    } else if (p == 1) {
        for (int idx = t; idx < 48 * 48; idx += 256) {
            const int j = idx / 48, d = idx % 48, u = d >> 4, i = d & 15;
            sArr[j * 48 + d] = b01[(base + j) * 3 + u] * xg[j * 16 + i];
        }
    } else if (p == 2) {
        for (int idx = t; idx < 48 * 16; idx += 256) {
            const int j = idx >> 4, i = idx & 15;
            const float* u = b10 + (base + j) * 3;
            const float* xr = xg + j * 48 + i * 3;
            sArr[idx] = mskf[j] * (u[0] * xr[0] + u[1] * xr[1] + u[2] * xr[2]);
        }
    } else {
        for (int idx = t; idx < 48 * 144; idx += 256) {
            const int j = idx / 144, d = idx % 144;
            const int a = d / 48, r = d % 48, i = r / 3, f = r % 3;
            const float* w = b11 + (base + j) * 27 + a * 9 + f;
            const float* xr = xg + j * 48 + i * 3;
            sArr[j * 144 + d] = mskf[j] * (w[0] * xr[0] + w[3] * xr[1] + w[6] * xr[2]);
        }
    }
    __syncthreads();

    if (p == 0 && t == 0) {
        float s = 0.f;
        for (int j = 0; j < 48; ++j) s += mskf[j];
        g_den[n] = s;
    }
    const int D = (p == 0) ? 16 : (p == 1) ? 48 : (p == 2) ? 16 : 144;
    const int off = (p == 0) ? 0 : (p == 1) ? 16 : (p == 2) ? 64 : 80;
    for (int d = t; d < D; d += 256) {
        float s = 0.f;
        for (int j = 0; j < 48; ++j) s += sArr[j * D + d];
        g_S[n * 224 + off + d] = s;
    }

    float* Pout = g_P + (size_t)n * MIDC * 224 + off;
    if (p == 0)      pgemm<16>(h2s, sArr, Pout, t);
    else if (p == 1) pgemm<48>(h2s, sArr, Pout, t);
    else if (p == 2) pgemm<16>(h2s, sArr, Pout, t);
    else             pgemm<144>(h2s, sArr, Pout, t);
}

// ---------------- k_F2: tiled contraction out_part = w3 . P ----------------
// grid (32 node-tiles, 32 mid-chunks of 4); 256 thr = 16 nodes x 16 o.
// smem floats: Ps[16n][4m][224] @0 (14336) | w00s[4][16][20] @14336 (1280)
//              w01s @15616 (1280) | w10s @16896 (1280) | w11s[4][16][60] @18176 (3840)
#define KF2_SMEM_FLOATS 22016

__device__ __forceinline__ float dot16r(const float* __restrict__ r, const float* __restrict__ p) {
    float a = 0.f;
    #pragma unroll
    for (int i = 0; i < 16; i += 4) {
        const float4 pv = *(const float4*)(p + i);
        a = fmaf(r[i],     pv.x, a); a = fmaf(r[i + 1], pv.y, a);
        a = fmaf(r[i + 2], pv.z, a); a = fmaf(r[i + 3], pv.w, a);
    }
    return a;
}
__device__ __forceinline__ float dot48r(const float* __restrict__ r, const float* __restrict__ p) {
    float a = 0.f;
    #pragma unroll
    for (int i = 0; i < 48; i += 4) {
        const float4 pv = *(const float4*)(p + i);
        a = fmaf(r[i],     pv.x, a); a = fmaf(r[i + 1], pv.y, a);
        a = fmaf(r[i + 2], pv.z, a); a = fmaf(r[i + 3], pv.w, a);
    }
    return a;
}

__global__ __launch_bounds__(256) void k_F2(
    const float* __restrict__ w300, const float* __restrict__ w301,
    const float* __restrict__ w310, const float* __restrict__ w311)
{
    extern __shared__ float sm[];
    float* Ps   = sm;
    float* w00s = sm + 14336;
    float* w01s = sm + 15616;
    float* w10s = sm + 16896;
    float* w11s = sm + 18176;

    const int tile = blockIdx.x, mc = blockIdx.y, t = threadIdx.x;
    const int mid0 = mc * 4;

    // stage w3 chunks (padded rows: 20 / 60 floats, float4-aligned)
    for (int i = t; i < 256; i += 256) {
        const int m = i >> 6, c = (i & 63) * 4;
        const int o = c >> 4, ii = c & 15;
        const float4 v0 = *(const float4*)(w300 + (mid0 + m) * 256 + c);
        const float4 v1 = *(const float4*)(w301 + (mid0 + m) * 256 + c);
        const float4 v2 = *(const float4*)(w310 + (mid0 + m) * 256 + c);
        *(float4*)(w00s + (m * 16 + o) * 20 + ii) = v0;
        *(float4*)(w01s + (m * 16 + o) * 20 + ii) = v1;
        *(float4*)(w10s + (m * 16 + o) * 20 + ii) = v2;
    }
    for (int i = t; i < 768; i += 256) {
        const int m = i / 192, c = (i % 192) * 4;
        const int o = c / 48, r = c % 48;
        const float4 v = *(const float4*)(w311 + (mid0 + m) * 768 + c);
        *(float4*)(w11s + (m * 16 + o) * 60 + r) = v;
    }
    // stage P tile: 16 nodes x 4 mids x 224
    {
        const float* src = g_P + (size_t)(tile * 16) * 28672 + mid0 * 224;
        for (int i = t; i < 3584; i += 256) {
            const int nm = i / 56, c4 = (i % 56) * 4;
            const int n = nm >> 2, m = nm & 3;
            *(float4*)(Ps + nm * 224 + c4) =
                *(const float4*)(src + (size_t)n * 28672 + m * 224 + c4);
        }
    }
    __syncthreads();

    const int nl = t >> 4, o = t & 15;
    float a0 = 0.f, a1 = 0.f, a2 = 0.f, a3 = 0.f;

    #pragma unroll 1
    for (int m = 0; m < 4; ++m) {
        const float* P  = Ps + (nl * 4 + m) * 224;
        const float* W0 = w00s + (m * 16 + o) * 20;
        const float* W2 = w10s + (m * 16 + o) * 20;
        // degree-0 output: pairs (0,0) and (1,0)
        #pragma unroll
        for (int i = 0; i < 16; i += 4) {
            const float4 w0 = *(const float4*)(W0 + i);
            const float4 p0 = *(const float4*)(P + i);
            const float4 w2 = *(const float4*)(W2 + i);
            const float4 p2 = *(const float4*)(P + 64 + i);
            a0 = fmaf(w0.x, p0.x, a0); a0 = fmaf(w0.y, p0.y, a0);
            a0 = fmaf(w0.z, p0.z, a0); a0 = fmaf(w0.w, p0.w, a0);
            a0 = fmaf(w2.x, p2.x, a0); a0 = fmaf(w2.y, p2.y, a0);
            a0 = fmaf(w2.z, p2.z, a0); a0 = fmaf(w2.w, p2.w, a0);
        }
        // degree-1 outputs: pair (0,1), w fragment reused for 3 components
        {
            const float* W1 = w01s + (m * 16 + o) * 20;
            float r01[16];
            #pragma unroll
            for (int i = 0; i < 16; i += 4) *(float4*)(r01 + i) = *(const float4*)(W1 + i);
            a1 += dot16r(r01, P + 16);
            a2 += dot16r(r01, P + 32);
            a3 += dot16r(r01, P + 48);
        }
        // degree-1 outputs: pair (1,1)
        {
            const float* W3 = w11s + (m * 16 + o) * 60;
            float r11[48];
            #pragma unroll
            for (int i = 0; i < 48; i += 4) *(float4*)(r11 + i) = *(const float4*)(W3 + i);
            a1 += dot48r(r11, P + 80);
            a2 += dot48r(r11, P + 128);
            a3 += dot48r(r11, P + 176);
        }
    }

    float* dst = g_part + (size_t)mc * (NN * 64) + (size_t)(tile * 16 + nl) * 64 + o * 4;
    dst[0] = a0; dst[1] = a1; dst[2] = a2; dst[3] = a3;
}

// ---------------- k_E: reduce partials + bias via S + mean + self ----------------
__global__ __launch_bounds__(256) void k_E(
    const float* __restrict__ x0, const float* __restrict__ x1,
    const float* __restrict__ b300, const float* __restrict__ b301,
    const float* __restrict__ b310, const float* __restrict__ b311,
    const float* __restrict__ ks0, const float* __restrict__ ks1,
    float* __restrict__ out)
{
    const int gid = blockIdx.x * 256 + threadIdx.x;   // 32768 total
    const int n = gid >> 6, w = gid & 63, o = w >> 2, d = w & 3;

    float acc = 0.f;
    #pragma unroll
    for (int mcx = 0; mcx < 32; ++mcx) acc += g_part[mcx * (NN * 64) + gid];

    const float dn = g_den[n];
    const float* Sv = g_S + n * 224;
    if (d == 0) {
        #pragma unroll
        for (int i = 0; i < 16; ++i) {
            acc = fmaf(b300[o * 16 + i], Sv[i], acc);
            acc = fmaf(b310[o * 16 + i], Sv[64 + i], acc);
        }
        acc /= dn;
        #pragma unroll
        for (int i = 0; i < 16; ++i) acc = fmaf(ks0[o * 16 + i], x0[n * 16 + i], acc);
    } else {
        const int a = d - 1;
        #pragma unroll
        for (int i = 0; i < 16; ++i) acc = fmaf(b301[o * 16 + i], Sv[16 + a * 16 + i], acc);
        #pragma unroll
        for (int r = 0; r < 48; ++r) acc = fmaf(b311[o * 48 + r], Sv[80 + a * 48 + r], acc);
        acc /= dn;
        #pragma unroll
        for (int i = 0; i < 16; ++i) acc = fmaf(ks1[o * 16 + i], x1[(n * 16 + i) * 3 + a], acc);
    }
    out[gid] = acc;
}

// ---------------- launch ----------------
extern "C" void kernel_launch(void* const* d_in, const int* in_sizes, int n_in,
                              void* d_out, int out_size)
{
    const float* x0    = (const float*)d_in[0];
    const float* x1    = (const float*)d_in[1];
    const float* rel   = (const float*)d_in[2];
    const int*   nidx  = (const int*)d_in[3];
    const void*  maskp = d_in[4];
    const float* b00   = (const float*)d_in[5];
    const float* b01   = (const float*)d_in[6];
    const float* b10   = (const float*)d_in[7];
    const float* b11   = (const float*)d_in[8];
    const float* w1    = (const float*)d_in[9];
    const float* b1    = (const float*)d_in[10];
    const float* g1    = (const float*)d_in[11];
    const float* be1   = (const float*)d_in[12];
    const float* w2    = (const float*)d_in[13];
    const float* b2    = (const float*)d_in[14];
    const float* g2    = (const float*)d_in[15];
    const float* be2   = (const float*)d_in[16];
    const float* w3_00 = (const float*)d_in[17];
    const float* b3_00 = (const float*)d_in[18];
    const float* w3_01 = (const float*)d_in[19];
    const float* b3_01 = (const float*)d_in[20];
    const float* w3_10 = (const float*)d_in[21];
    const float* b3_10 = (const float*)d_in[22];
    const float* w3_11 = (const float*)d_in[23];
    const float* b3_11 = (const float*)d_in[24];
    const float* ks0   = (const float*)d_in[25];
    const float* ks1   = (const float*)d_in[26];
    float* out = (float*)d_out;

    const int smP  = KP_SMEM_FLOATS * 4;
    const int smF2 = KF2_SMEM_FLOATS * 4;
    cudaFuncSetAttribute(k_P,  cudaFuncAttributeMaxDynamicSharedMemorySize, smP);
    cudaFuncSetAttribute(k_F2, cudaFuncAttributeMaxDynamicSharedMemorySize, smF2);

    k1_mlp<<<EE / 32, 256>>>(rel, (const unsigned char*)maskp,
                             w1, b1, g1, be1, w2, b2, g2, be2);
    k_P<<<dim3(NN, 4), 256, smP>>>(x0, x1, nidx, maskp, b00, b01, b10, b11);
    k_F2<<<dim3(32, 32), 256, smF2>>>(w3_00, w3_01, w3_10, w3_11);
    k_E<<<128, 256>>>(x0, x1, b3_00, b3_01, b3_10, b3_11, ks0, ks1, out);
}

// round 13
// speedup vs baseline: 1.3067x; 1.3067x over previous
#include <cuda_runtime.h>
#include <cstdint>

#define NN   512
#define JJ   48
#define EE   (NN*JJ)
#define MIDC 128
#define EPSL 1e-5f

// ---------------- device scratch ----------------
__device__ int g_mask_mode;                         // 0 = 1-byte bool, 1 = float32, 2 = int32
__device__ __align__(16) float g_h2[(size_t)4 * EE * MIDC];   // ~50 MB
__device__ __align__(16) float g_P[(size_t)NN * MIDC * 224];  // ~59 MB
__device__ __align__(16) float g_S[NN * 224];
__device__ float g_den[NN];
__device__ __align__(16) float g_part[16 * NN * 64];          // per-mid-chunk partials (2 MB)

// ---------------- tf32 mma helpers (portable PTX, sm_80+) ----------------
__device__ __forceinline__ uint32_t f2tf32(float x) {
    uint32_t r;
    asm("cvt.rna.tf32.f32 %0, %1;" : "=r"(r) : "f"(x));
    return r;
}
__device__ __forceinline__ void mma8(float* c, const uint32_t* a, uint32_t b0, uint32_t b1) {
    asm volatile(
        "mma.sync.aligned.m16n8k8.row.col.f32.tf32.tf32.f32 "
        "{%0,%1,%2,%3}, {%4,%5,%6,%7}, {%8,%9}, {%0,%1,%2,%3};"
        : "+f"(c[0]), "+f"(c[1]), "+f"(c[2]), "+f"(c[3])
        : "r"(a[0]), "r"(a[1]), "r"(a[2]), "r"(a[3]), "r"(b0), "r"(b1));
}

// ---------------- K1: per-edge radial MLP, w2 GEMM on tensor cores ----------------
// grid (384, 4): 64 edges x one pair per block; 128 threads (4 warps).
// smem: h1s[64][132] (33792 B) | w2s[128][136] (69632 B)  -> 103424 B total
#define K1E 64
#define SA  132
#define SB  136
#define K1_SMEM ((K1E * SA + 128 * SB) * 4)

__global__ __launch_bounds__(128) void k1_mma(
    const float* __restrict__ rel, const unsigned char* __restrict__ mb,
    const float* __restrict__ w1, const float* __restrict__ b1,
    const float* __restrict__ g1, const float* __restrict__ be1,
    const float* __restrict__ w2, const float* __restrict__ b2,
    const float* __restrict__ g2, const float* __restrict__ be2)
{
    extern __shared__ float sm[];
    float* h1s = sm;                  // stride SA
    float* w2s = sm + K1E * SA;       // stride SB

    const int t = threadIdx.x, lane = t & 31, wp = t >> 5;
    const int p = blockIdx.y;
    const int e0 = blockIdx.x * K1E;
    const int g = lane >> 2, tid = lane & 3;

    // mask dtype detection (block (0,0), warp 0)
    if (blockIdx.x == 0 && p == 0 && wp == 0) {
        int l1 = 0, l3 = 0;
        for (int i = lane * 4; i < 8192; i += 128) {
            if (mb[i + 1]) l1++;              // nonzero -> 1-byte bool data
            if (mb[i + 3] == 0x3Fu) l3++;     // top byte of float 1.0f
        }
        const unsigned u1 = __ballot_sync(0xffffffffu, l1 > 0);
        const unsigned u3 = __ballot_sync(0xffffffffu, l3 > 0);
        if (lane == 0) g_mask_mode = u1 ? 0 : (u3 ? 1 : 2);
    }

    // stage w2[p] (128x128 row-major: [k][n]) into padded smem
    {
        const float4* wsrc = (const float4*)(w2 + (size_t)p * MIDC * MIDC);
        for (int i = t; i < 4096; i += 128) {
            const int row = i >> 5, c4 = (i & 31) * 4;
            *(float4*)(w2s + row * SB + c4) = wsrc[i];
        }
    }

    // phase A: h1 = relu(LN(d*w1+b1)) for this warp's 16 edges
    {
        const float* w1p = w1 + p * MIDC;  const float* b1p = b1 + p * MIDC;
        const float* g1p = g1 + p * MIDC;  const float* be1p = be1 + p * MIDC;
        for (int q = 0; q < 16; ++q) {
            const int le = wp * 16 + q;
            const float d = rel[e0 + le];
            float a[4];
            #pragma unroll
            for (int s_ = 0; s_ < 4; ++s_) {
                int c = lane + 32 * s_;
                a[s_] = fmaf(d, w1p[c], b1p[c]);
            }
            float s = a[0] + a[1] + a[2] + a[3];
            float s2 = a[0]*a[0] + a[1]*a[1] + a[2]*a[2] + a[3]*a[3];
            #pragma unroll
            for (int off = 16; off; off >>= 1) {
                s  += __shfl_xor_sync(0xffffffffu, s,  off);
                s2 += __shfl_xor_sync(0xffffffffu, s2, off);
            }
            const float mu  = s * 0.0078125f;
            const float inv = rsqrtf(fmaf(-mu, mu, s2 * 0.0078125f) + EPSL);
            #pragma unroll
            for (int s_ = 0; s_ < 4; ++s_) {
                int c = lane + 32 * s_;
                h1s[le * SA + c] = fmaxf(fmaf((a[s_] - mu) * inv, g1p[c], be1p[c]), 0.f);
            }
        }
    }
    __syncthreads();

    // GEMM: warp wp owns m16 tile (edges m0..m0+15), full N=128, K=128, tf32 x3
    const int m0 = wp * 16;
    float acc[16][4];
    #pragma unroll
    for (int n = 0; n < 16; ++n)
        acc[n][0] = acc[n][1] = acc[n][2] = acc[n][3] = 0.f;

    const int rA = (m0 + g) * SA, rB = (m0 + g + 8) * SA;
    #pragma unroll 1
    for (int k = 0; k < 16; ++k) {
        const int kc = k * 8 + tid;
        const float fa0 = h1s[rA + kc],     fa1 = h1s[rB + kc];
        const float fa2 = h1s[rA + kc + 4], fa3 = h1s[rB + kc + 4];
        uint32_t ahi[4] = { f2tf32(fa0), f2tf32(fa1), f2tf32(fa2), f2tf32(fa3) };
        uint32_t alo[4] = { f2tf32(fa0 - __uint_as_float(ahi[0])),
                            f2tf32(fa1 - __uint_as_float(ahi[1])),
                            f2tf32(fa2 - __uint_as_float(ahi[2])),
                            f2tf32(fa3 - __uint_as_float(ahi[3])) };
        const float* wrow0 = w2s + kc * SB;
        const float* wrow1 = w2s + (kc + 4) * SB;
        #pragma unroll
        for (int n = 0; n < 16; ++n) {
            const float fb0 = wrow0[n * 8 + g];
            const float fb1 = wrow1[n * 8 + g];
            const uint32_t bh0 = f2tf32(fb0), bh1 = f2tf32(fb1);
            const uint32_t bl0 = f2tf32(fb0 - __uint_as_float(bh0));
            const uint32_t bl1 = f2tf32(fb1 - __uint_as_float(bh1));
            mma8(acc[n], ahi, bh0, bh1);
            mma8(acc[n], alo, bh0, bh1);
            mma8(acc[n], ahi, bl0, bl1);
        }
    }

    // epilogue: +b2, LN over 128 cols (4-lane shfl groups own each row), relu, store
    const float* b2p  = b2  + p * MIDC;
    const float* g2p  = g2  + p * MIDC;
    const float* be2p = be2 + p * MIDC;
    float sA = 0.f, qA = 0.f, sB = 0.f, qB = 0.f;
    #pragma unroll
    for (int n = 0; n < 16; ++n) {
        const int c0 = n * 8 + tid * 2;
        const float bb0 = b2p[c0], bb1 = b2p[c0 + 1];
        acc[n][0] += bb0; acc[n][1] += bb1;
        acc[n][2] += bb0; acc[n][3] += bb1;
        sA += acc[n][0] + acc[n][1];
        qA += acc[n][0]*acc[n][0] + acc[n][1]*acc[n][1];
        sB += acc[n][2] + acc[n][3];
        qB += acc[n][2]*acc[n][2] + acc[n][3]*acc[n][3];
    }
    #pragma unroll
    for (int off = 1; off < 4; off <<= 1) {
        sA += __shfl_xor_sync(0xffffffffu, sA, off);
        qA += __shfl_xor_sync(0xffffffffu, qA, off);
        sB += __shfl_xor_sync(0xffffffffu, sB, off);
        qB += __shfl_xor_sync(0xffffffffu, qB, off);
    }
    const float muA = sA * 0.0078125f;
    const float invA = rsqrtf(fmaf(-muA, muA, qA * 0.0078125f) + EPSL);
    const float muB = sB * 0.0078125f;
    const float invB = rsqrtf(fmaf(-muB, muB, qB * 0.0078125f) + EPSL);

    float* oA = g_h2 + ((size_t)p * EE + e0 + m0 + g) * MIDC;
    float* oB = oA + 8 * MIDC;
    #pragma unroll
    for (int n = 0; n < 16; ++n) {
        const int c0 = n * 8 + tid * 2;
        const float gg0 = g2p[c0], gg1 = g2p[c0 + 1];
        const float ee0 = be2p[c0], ee1 = be2p[c0 + 1];
        float2 vA, vB;
        vA.x = fmaxf(fmaf((acc[n][0] - muA) * invA, gg0, ee0), 0.f);
        vA.y = fmaxf(fmaf((acc[n][1] - muA) * invA, gg1, ee1), 0.f);
        vB.x = fmaxf(fmaf((acc[n][2] - muB) * invB, gg0, ee0), 0.f);
        vB.y = fmaxf(fmaf((acc[n][3] - muB) * invB, gg1, ee1), 0.f);
        *(float2*)(oA + c0) = vA;
        *(float2*)(oB + c0) = vB;
    }
}

// ---------------- kP: per-(node,pair) P = h2^T @ s, plus S sums + denom ----------------
template<int D>
__device__ __forceinline__ void pgemm(const float* __restrict__ h2s,
                                      const float* __restrict__ sArr,
                                      float* __restrict__ Pout, int t)
{
    constexpr int DPT = D / 8;
    const int mid0 = (t & 31) * 4, d0 = (t >> 5) * DPT;
    float acc[4][DPT];
    #pragma unroll
    for (int m = 0; m < 4; ++m)
        #pragma unroll
        for (int d = 0; d < DPT; ++d) acc[m][d] = 0.f;

    #pragma unroll 2
    for (int j = 0; j < JJ; ++j) {
        const float4 hv = *(const float4*)(h2s + j * MIDC + mid0);
        float sv[DPT];
        #pragma unroll
        for (int d = 0; d < DPT; ++d) sv[d] = sArr[j * D + d0 + d];
        #pragma unroll
        for (int d = 0; d < DPT; ++d) {
            acc[0][d] = fmaf(hv.x, sv[d], acc[0][d]);
            acc[1][d] = fmaf(hv.y, sv[d], acc[1][d]);
            acc[2][d] = fmaf(hv.z, sv[d], acc[2][d]);
            acc[3][d] = fmaf(hv.w, sv[d], acc[3][d]);
        }
    }
    #pragma unroll
    for (int m = 0; m < 4; ++m)
        #pragma unroll
        for (int d = 0; d < DPT; ++d)
            Pout[(size_t)(mid0 + m) * 224 + d0 + d] = acc[m][d];
}

#define KP_SMEM_FLOATS 15424

__global__ __launch_bounds__(256) void k_P(
    const float* __restrict__ x0, const float* __restrict__ x1,
    const int* __restrict__ nidx, const void* __restrict__ maskp,
    const float* __restrict__ b00, const float* __restrict__ b01,
    const float* __restrict__ b10, const float* __restrict__ b11)
{
    extern __shared__ float sm[];
    float* h2s  = sm;
    float* sArr = sm + 6144;
    float* xg   = sm + 13056;
    float* mskf = sm + 15360;

    const int n = blockIdx.x, p = blockIdx.y, t = threadIdx.x;
    const int base = n * JJ;

    {
        const float4* src = (const float4*)(g_h2 + ((size_t)p * EE + base) * MIDC);
        float4* dst = (float4*)h2s;
        #pragma unroll
        for (int i = t; i < 1536; i += 256) dst[i] = src[i];
    }
    if (t < 48) {
        const int j = t;
        const int mode = g_mask_mode;
        float mf;
        if (mode == 0)      mf = ((const unsigned char*)maskp)[base + j] ? 1.f : 0.f;
        else if (mode == 1) mf = (((const float*)maskp)[base + j] != 0.f) ? 1.f : 0.f;
        else                mf = ((const int*)maskp)[base + j] ? 1.f : 0.f;
        mskf[j] = mf;
        const int nb = nidx[base + j];
        if (p < 2) {
            #pragma unroll
            for (int i = 0; i < 16; ++i) xg[j * 16 + i] = mf * x0[nb * 16 + i];
        } else {
            #pragma unroll
            for (int i = 0; i < 48; ++i) xg[j * 48 + i] = x1[nb * 48 + i];
        }
    }
    __syncthreads();

    if (p == 0) {
        for (int idx = t; idx < 48 * 16; idx += 256) {
            const int j = idx >> 4, i = idx & 15;
            sArr[idx] = b00[base + j] * xg[j * 16 + i];
        }
    } else if (p == 1) {
        for (int idx = t; idx < 48 * 48; idx += 256) {
            const int j = idx / 48, d = idx % 48, u = d >> 4, i = d & 15;
            sArr[j * 48 + d] = b01[(base + j) * 3 + u] * xg[j * 16 + i];
        }
    } else if (p == 2) {
        for (int idx = t; idx < 48 * 16; idx += 256) {
            const int j = idx >> 4, i = idx & 15;
            const float* u = b10 + (base + j) * 3;
            const float* xr = xg + j * 48 + i * 3;
            sArr[idx] = mskf[j] * (u[0] * xr[0] + u[1] * xr[1] + u[2] * xr[2]);
        }
    } else {
        for (int idx = t; idx < 48 * 144; idx += 256) {
            const int j = idx / 144, d = idx % 144;
            const int a = d / 48, r = d % 48, i = r / 3, f = r % 3;
            const float* w = b11 + (base + j) * 27 + a * 9 + f;
            const float* xr = xg + j * 48 + i * 3;
            sArr[j * 144 + d] = mskf[j] * (w[0] * xr[0] + w[3] * xr[1] + w[6] * xr[2]);
        }
    }
    __syncthreads();

    if (p == 0 && t == 0) {
        float s = 0.f;
        for (int j = 0; j < 48; ++j) s += mskf[j];
        g_den[n] = s;
    }
    const int D = (p == 0) ? 16 : (p == 1) ? 48 : (p == 2) ? 16 : 144;
    const int off = (p == 0) ? 0 : (p == 1) ? 16 : (p == 2) ? 64 : 80;
    for (int d = t; d < D; d += 256) {
        float s = 0.f;
        for (int j = 0; j < 48; ++j) s += sArr[j * D + d];
        g_S[n * 224 + off + d] = s;
    }

    float* Pout = g_P + (size_t)n * MIDC * 224 + off;
    if (p == 0)      pgemm<16>(h2s, sArr, Pout, t);
    else if (p == 1) pgemm<48>(h2s, sArr, Pout, t);
    else if (p == 2) pgemm<16>(h2s, sArr, Pout, t);
    else             pgemm<144>(h2s, sArr, Pout, t);
}

// ---------------- k_F2: tiled contraction out_part = w3 . P (R11-measured config) ----
#define KF2_SMEM_FLOATS 44032

__device__ __forceinline__ float dot16r(const float* __restrict__ r, const float* __restrict__ p) {
    float a = 0.f;
    #pragma unroll
    for (int i = 0; i < 16; i += 4) {
        const float4 pv = *(const float4*)(p + i);
        a = fmaf(r[i],     pv.x, a); a = fmaf(r[i + 1], pv.y, a);
        a = fmaf(r[i + 2], pv.z, a); a = fmaf(r[i + 3], pv.w, a);
    }
    return a;
}
__device__ __forceinline__ float dot48r(const float* __restrict__ r, const float* __restrict__ p) {
    float a = 0.f;
    #pragma unroll
    for (int i = 0; i < 48; i += 4) {
        const float4 pv = *(const float4*)(p + i);
        a = fmaf(r[i],     pv.x, a); a = fmaf(r[i + 1], pv.y, a);
        a = fmaf(r[i + 2], pv.z, a); a = fmaf(r[i + 3], pv.w, a);
    }
    return a;
}

__global__ __launch_bounds__(256) void k_F2(
    const float* __restrict__ w300, const float* __restrict__ w301,
    const float* __restrict__ w310, const float* __restrict__ w311)
{
    extern __shared__ float sm[];
    float* Ps   = sm;
    float* w00s = sm + 28672;
    float* w01s = sm + 31232;
    float* w10s = sm + 33792;
    float* w11s = sm + 36352;

    const int tile = blockIdx.x, mc = blockIdx.y, t = threadIdx.x;
    const int mid0 = mc * 8;

    for (int i = t; i < 512; i += 256) {
        const int m = i >> 6, c = (i & 63) * 4;
        const int o = c >> 4, ii = c & 15;
        const float4 v0 = *(const float4*)(w300 + (mid0 + m) * 256 + c);
        const float4 v1 = *(const float4*)(w301 + (mid0 + m) * 256 + c);
        const float4 v2 = *(const float4*)(w310 + (mid0 + m) * 256 + c);
        *(float4*)(w00s + (m * 16 + o) * 20 + ii) = v0;
        *(float4*)(w01s + (m * 16 + o) * 20 + ii) = v1;
        *(float4*)(w10s + (m * 16 + o) * 20 + ii) = v2;
    }
    for (int i = t; i < 1536; i += 256) {
        const int m = i / 192, c = (i % 192) * 4;
        const int o = c / 48, r = c % 48;
        const float4 v = *(const float4*)(w311 + (mid0 + m) * 768 + c);
        *(float4*)(w11s + (m * 16 + o) * 60 + r) = v;
    }
    {
        const float* src = g_P + (size_t)(tile * 16) * 28672 + mid0 * 224;
        for (int i = t; i < 7168; i += 256) {
            const int nm = i / 56, c4 = (i % 56) * 4;
            const int n = nm >> 3, m = nm & 7;
            *(float4*)(Ps + nm * 224 + c4) =
                *(const float4*)(src + (size_t)n * 28672 + m * 224 + c4);
        }
    }
    __syncthreads();

    const int nl = t >> 4, o = t & 15;
    float a0 = 0.f, a1 = 0.f, a2 = 0.f, a3 = 0.f;

    #pragma unroll 1
    for (int m = 0; m < 8; ++m) {
        const float* P  = Ps + (nl * 8 + m) * 224;
        const float* W0 = w00s + (m * 16 + o) * 20;
        const float* W2 = w10s + (m * 16 + o) * 20;
        #pragma unroll
        for (int i = 0; i < 16; i += 4) {
            const float4 w0 = *(const float4*)(W0 + i);
            const float4 p0 = *(const float4*)(P + i);
            const float4 w2v = *(const float4*)(W2 + i);
            const float4 p2 = *(const float4*)(P + 64 + i);
            a0 = fmaf(w0.x, p0.x, a0); a0 = fmaf(w0.y, p0.y, a0);
            a0 = fmaf(w0.z, p0.z, a0); a0 = fmaf(w0.w, p0.w, a0);
            a0 = fmaf(w2v.x, p2.x, a0); a0 = fmaf(w2v.y, p2.y, a0);
            a0 = fmaf(w2v.z, p2.z, a0); a0 = fmaf(w2v.w, p2.w, a0);
        }
        {
            const float* W1 = w01s + (m * 16 + o) * 20;
            float r01[16];
            #pragma unroll
            for (int i = 0; i < 16; i += 4) *(float4*)(r01 + i) = *(const float4*)(W1 + i);
            a1 += dot16r(r01, P + 16);
            a2 += dot16r(r01, P + 32);
            a3 += dot16r(r01, P + 48);
        }
        {
            const float* W3 = w11s + (m * 16 + o) * 60;
            float r11[48];
            #pragma unroll
            for (int i = 0; i < 48; i += 4) *(float4*)(r11 + i) = *(const float4*)(W3 + i);
            a1 += dot48r(r11, P + 80);
            a2 += dot48r(r11, P + 128);
            a3 += dot48r(r11, P + 176);
        }
    }

    float* dst = g_part + (size_t)mc * (NN * 64) + (size_t)(tile * 16 + nl) * 64 + o * 4;
    dst[0] = a0; dst[1] = a1; dst[2] = a2; dst[3] = a3;
}

// ---------------- k_E: reduce partials + bias via S + mean + self ----------------
__global__ __launch_bounds__(256) void k_E(
    const float* __restrict__ x0, const float* __restrict__ x1,
    const float* __restrict__ b300, const float* __restrict__ b301,
    const float* __restrict__ b310, const float* __restrict__ b311,
    const float* __restrict__ ks0, const float* __restrict__ ks1,
    float* __restrict__ out)
{
    const int gid = blockIdx.x * 256 + threadIdx.x;   // 32768 total
    const int n = gid >> 6, w = gid & 63, o = w >> 2, d = w & 3;

    float acc = 0.f;
    #pragma unroll
    for (int mcx = 0; mcx < 16; ++mcx) acc += g_part[mcx * (NN * 64) + gid];

    const float dn = g_den[n];
    const float* Sv = g_S + n * 224;
    if (d == 0) {
        #pragma unroll
        for (int i = 0; i < 16; ++i) {
            acc = fmaf(b300[o * 16 + i], Sv[i], acc);
            acc = fmaf(b310[o * 16 + i], Sv[64 + i], acc);
        }
        acc /= dn;
        #pragma unroll
        for (int i = 0; i < 16; ++i) acc = fmaf(ks0[o * 16 + i], x0[n * 16 + i], acc);
    } else {
        const int a = d - 1;
        #pragma unroll
        for (int i = 0; i < 16; ++i) acc = fmaf(b301[o * 16 + i], Sv[16 + a * 16 + i], acc);
        #pragma unroll
        for (int r = 0; r < 48; ++r) acc = fmaf(b311[o * 48 + r], Sv[80 + a * 48 + r], acc);
        acc /= dn;
        #pragma unroll
        for (int i = 0; i < 16; ++i) acc = fmaf(ks1[o * 16 + i], x1[(n * 16 + i) * 3 + a], acc);
    }
    out[gid] = acc;
}

// ---------------- launch ----------------
extern "C" void kernel_launch(void* const* d_in, const int* in_sizes, int n_in,
                              void* d_out, int out_size)
{
    const float* x0    = (const float*)d_in[0];
    const float* x1    = (const float*)d_in[1];
    const float* rel   = (const float*)d_in[2];
    const int*   nidx  = (const int*)d_in[3];
    const void*  maskp = d_in[4];
    const float* b00   = (const float*)d_in[5];
    const float* b01   = (const float*)d_in[6];
    const float* b10   = (const float*)d_in[7];
    const float* b11   = (const float*)d_in[8];
    const float* w1    = (const float*)d_in[9];
    const float* b1    = (const float*)d_in[10];
    const float* g1    = (const float*)d_in[11];
    const float* be1   = (const float*)d_in[12];
    const float* w2    = (const float*)d_in[13];
    const float* b2    = (const float*)d_in[14];
    const float* g2    = (const float*)d_in[15];
    const float* be2   = (const float*)d_in[16];
    const float* w3_00 = (const float*)d_in[17];
    const float* b3_00 = (const float*)d_in[18];
    const float* w3_01 = (const float*)d_in[19];
    const float* b3_01 = (const float*)d_in[20];
    const float* w3_10 = (const float*)d_in[21];
    const float* b3_10 = (const float*)d_in[22];
    const float* w3_11 = (const float*)d_in[23];
    const float* b3_11 = (const float*)d_in[24];
    const float* ks0   = (const float*)d_in[25];
    const float* ks1   = (const float*)d_in[26];
    float* out = (float*)d_out;

    const int smP  = KP_SMEM_FLOATS * 4;
    const int smF2 = KF2_SMEM_FLOATS * 4;
    cudaFuncSetAttribute(k1_mma, cudaFuncAttributeMaxDynamicSharedMemorySize, K1_SMEM);
    cudaFuncSetAttribute(k_P,  cudaFuncAttributeMaxDynamicSharedMemorySize, smP);
    cudaFuncSetAttribute(k_F2, cudaFuncAttributeMaxDynamicSharedMemorySize, smF2);

    k1_mma<<<dim3(EE / K1E, 4), 128, K1_SMEM>>>(rel, (const unsigned char*)maskp,
                                                w1, b1, g1, be1, w2, b2, g2, be2);
    k_P<<<dim3(NN, 4), 256, smP>>>(x0, x1, nidx, maskp, b00, b01, b10, b11);
    k_F2<<<dim3(32, 16), 256, smF2>>>(w3_00, w3_01, w3_10, w3_11);
    k_E<<<128, 256>>>(x0, x1, b3_00, b3_01, b3_10, b3_11, ks0, ks1, out);
}